// round 6
// baseline (speedup 1.0000x reference)
#include <cuda_runtime.h>
#include <cstdint>
#include <cstddef>

// Problem constants (fixed by the dataset generator)
#define VOCAB 50000
#define D     300
#define BATCH 64
#define LC    32
#define TT    256
#define LT    64
#define NSEL  5

// Scratch (no allocations allowed -> device globals)
__device__ float g_scores[BATCH * TT];
__device__ int   g_topidx[BATCH * NSEL];

// ---------------------------------------------------------------------------
// f32x2 packed-FMA helpers (sm_103a FFMA2 — only reachable via PTX)
// ---------------------------------------------------------------------------
__device__ __forceinline__ unsigned long long pack2(float x, float y) {
    unsigned long long r;
    asm("mov.b64 %0, {%1, %2};" : "=l"(r) : "f"(x), "f"(y));
    return r;
}
__device__ __forceinline__ void unpack2(unsigned long long v, float& x, float& y) {
    asm("mov.b64 {%0, %1}, %2;" : "=f"(x), "=f"(y) : "l"(v));
}
__device__ __forceinline__ void ffma2(unsigned long long& d,
                                      unsigned long long a,
                                      unsigned long long b) {
    asm("fma.rn.f32x2 %0, %1, %2, %0;" : "+l"(d) : "l"(a), "l"(b));
}

// ---------------------------------------------------------------------------
// Pass 1: per (b,t) tile compute U = c . t^T  [32 x 64], fused softmax over l,
// max over c, sum over l  ->  g_scores[b*T + t].
// One warp per tile, 4 tiles (same b) per 128-thread block. Register fragment
// 8c x 8l per lane, kept as 8x4 packed f32x2 accumulators.
//
// SMEM is k-major with an XOR swizzle in 4-float column groups:
//   physical col = 4*((col>>2) ^ (row>>2)) + (col&3)
// This makes the transpose STS fully bank-conflict-free (verified: the 32
// lanes of each staging STS hit 32 distinct banks) while compute LDS.128
// stays 16B-aligned and <=2-way conflicted.
// ---------------------------------------------------------------------------
__global__ __launch_bounds__(128, 3)
void scores_kernel(const int* __restrict__ claim,
                   const int* __restrict__ targets,
                   const float* __restrict__ emb)
{
    __shared__ __align__(16) float sA[32 * 32];       // [k][c] swizzled
    __shared__ __align__(16) float sB[4][32 * 64];    // [tile][k][l] swizzled
    __shared__ int s_cid[LC];
    __shared__ int s_tid[4 * LT];

    const int b      = blockIdx.y;
    const int t_base = blockIdx.x * 4;
    const int tid    = threadIdx.x;
    const int warp   = tid >> 5;
    const int lane   = tid & 31;
    const int cg     = lane >> 3;      // claim group: c0 = 8*cg
    const int lg     = lane & 7;       // l group:     l0 = 8*lg

    if (tid < LC) s_cid[tid] = claim[b * LC + tid];
    for (int u = tid; u < 4 * LT; u += 128) {
        int tt = u >> 6, l = u & 63;
        s_tid[u] = targets[((size_t)b * TT + (t_base + tt)) * LT + l];
    }
    __syncthreads();

    unsigned long long acc2[8][4];     // [c_i][l_pair] packed {l even, l odd}
#pragma unroll
    for (int i = 0; i < 8; ++i)
#pragma unroll
        for (int j = 0; j < 4; ++j) acc2[i][j] = 0ull;

    const float4 zero4 = make_float4(0.f, 0.f, 0.f, 0.f);

    for (int chunk = 0; chunk < 10; ++chunk) {
        const int k0    = chunk * 32;
        const int kmax4 = (D - k0 + 3) >> 2;   // valid float4s this chunk (8 or 3)
        __syncthreads();                        // protect previous chunk's smem

        // Stage sA: 32 c-rows x 8 float4. Thread (c, q) writes k-rows 4q..4q+3
        // at swizzled col 4*((c>>2)^q) + (c&3). Conflict-free.
#pragma unroll
        for (int it = 0; it < 2; ++it) {
            int u = it * 128 + tid;
            int c = u >> 3, q = u & 7;
            const float4* p = (const float4*)(emb + (size_t)s_cid[c] * D + k0) + q;
            float4 v = (q < kmax4) ? __ldg(p) : zero4;
            int col = (((c >> 2) ^ q) << 2) | (c & 3);
            sA[(4 * q + 0) * 32 + col] = v.x;
            sA[(4 * q + 1) * 32 + col] = v.y;
            sA[(4 * q + 2) * 32 + col] = v.z;
            sA[(4 * q + 3) * 32 + col] = v.w;
        }
        // Stage sB: 256 l-rows x 8 float4. Same swizzle, conflict-free.
#pragma unroll
        for (int it = 0; it < 16; ++it) {
            int u  = it * 128 + tid;
            int lr = u >> 3, q = u & 7;         // lr = tile*64 + l
            const float4* p = (const float4*)(emb + (size_t)s_tid[lr] * D + k0) + q;
            float4 v = (q < kmax4) ? __ldg(p) : zero4;
            int l   = lr & 63;
            int col = ((((l >> 2) ^ q) & 15) << 2) | (l & 3);
            float* dst = &sB[lr >> 6][0];
            dst[(4 * q + 0) * 64 + col] = v.x;
            dst[(4 * q + 1) * 64 + col] = v.y;
            dst[(4 * q + 2) * 64 + col] = v.z;
            dst[(4 * q + 3) * 64 + col] = v.w;
        }
        __syncthreads();

        const float* Bw = sB[warp];
#pragma unroll 4
        for (int kk = 0; kk < 32; ++kk) {
            const int s = kk >> 2;
            float4 a0 = *(const float4*)&sA[kk * 32 + (((2 * cg)     ^ s) << 2)];
            float4 a1 = *(const float4*)&sA[kk * 32 + (((2 * cg + 1) ^ s) << 2)];
            ulonglong2 b0 = *(const ulonglong2*)&Bw[kk * 64 + (((2 * lg)     ^ s) << 2)];
            ulonglong2 b1 = *(const ulonglong2*)&Bw[kk * 64 + (((2 * lg + 1) ^ s) << 2)];
            float av[8] = {a0.x, a0.y, a0.z, a0.w, a1.x, a1.y, a1.z, a1.w};
            unsigned long long bp[4] = {b0.x, b0.y, b1.x, b1.y};
#pragma unroll
            for (int i = 0; i < 8; ++i) {
                unsigned long long ap = pack2(av[i], av[i]);
#pragma unroll
                for (int j = 0; j < 4; ++j) ffma2(acc2[i][j], ap, bp[j]);
            }
        }
    }

    // Unpack accumulators to scalar fragment acc[8][8]
    float acc[8][8];
#pragma unroll
    for (int i = 0; i < 8; ++i)
#pragma unroll
        for (int j = 0; j < 4; ++j)
            unpack2(acc2[i][j], acc[i][2 * j], acc[i][2 * j + 1]);

    // Row stats per c (over all 64 l): lanes sharing cg form an 8-lane group.
    float rinv[8];
#pragma unroll
    for (int i = 0; i < 8; ++i) {
        float m = acc[i][0];
#pragma unroll
        for (int j = 1; j < 8; ++j) m = fmaxf(m, acc[i][j]);
        m = fmaxf(m, __shfl_xor_sync(0xffffffffu, m, 1));
        m = fmaxf(m, __shfl_xor_sync(0xffffffffu, m, 2));
        m = fmaxf(m, __shfl_xor_sync(0xffffffffu, m, 4));
        float s = 0.f;
#pragma unroll
        for (int j = 0; j < 8; ++j) {
            acc[i][j] = __expf(acc[i][j] - m);   // overwrite U with exp(U - rowmax)
            s += acc[i][j];
        }
        s += __shfl_xor_sync(0xffffffffu, s, 1);
        s += __shfl_xor_sync(0xffffffffu, s, 2);
        s += __shfl_xor_sync(0xffffffffu, s, 4);
        rinv[i] = 1.0f / s;
    }

    // Column max over all 32 c (cross-cg via xor 8,16), then sum over 64 l.
    float colsum = 0.f;
#pragma unroll
    for (int j = 0; j < 8; ++j) {
        float cm = acc[0][j] * rinv[0];
#pragma unroll
        for (int i = 1; i < 8; ++i) cm = fmaxf(cm, acc[i][j] * rinv[i]);
        cm = fmaxf(cm, __shfl_xor_sync(0xffffffffu, cm, 8));
        cm = fmaxf(cm, __shfl_xor_sync(0xffffffffu, cm, 16));
        colsum += cm;
    }
    colsum += __shfl_xor_sync(0xffffffffu, colsum, 1);
    colsum += __shfl_xor_sync(0xffffffffu, colsum, 2);
    colsum += __shfl_xor_sync(0xffffffffu, colsum, 4);

    if (lane == 0) g_scores[b * TT + t_base + warp] = colsum;
}

// ---------------------------------------------------------------------------
// Pass 2: per-b top-5 of 256 scores, sorted descending (matches jax top_k;
// ties -> lowest index). One warp per b; each lane holds 8 scores.
// ---------------------------------------------------------------------------
__global__ void topk_kernel()
{
    const int b    = blockIdx.x;
    const int lane = threadIdx.x;
    float v[8];
#pragma unroll
    for (int j = 0; j < 8; ++j) v[j] = g_scores[b * TT + lane * 8 + j];

    for (int r = 0; r < NSEL; ++r) {
        float bm = v[0];
        int   bi = lane * 8;
#pragma unroll
        for (int j = 1; j < 8; ++j)
            if (v[j] > bm) { bm = v[j]; bi = lane * 8 + j; }
#pragma unroll
        for (int s = 16; s >= 1; s >>= 1) {
            float om = __shfl_xor_sync(0xffffffffu, bm, s);
            int   oi = __shfl_xor_sync(0xffffffffu, bi, s);
            if (om > bm || (om == bm && oi < bi)) { bm = om; bi = oi; }
        }
        if (lane == 0) g_topidx[b * NSEL + r] = bi;
        if ((bi >> 3) == lane) v[bi & 7] = -3.402823466e38f;
    }
}

// ---------------------------------------------------------------------------
// Pass 3: recompute U for the 5 selected t per b, L2-normalize each c-row
// over l, write [B,5,32,64]. One block per b, 5 warps (one per selected t).
// ~1% of pass-1 work: kept scalar/simple.
// ---------------------------------------------------------------------------
__global__ __launch_bounds__(160, 2)
void output_kernel(const int* __restrict__ claim,
                   const int* __restrict__ targets,
                   const float* __restrict__ emb,
                   float* __restrict__ out)
{
    __shared__ __align__(16) float sA[32][32];
    __shared__ __align__(16) float sB[NSEL][32][64];
    __shared__ int s_cid[LC];
    __shared__ int s_tid[NSEL * LT];
    __shared__ int s_sel[NSEL];

    const int b    = blockIdx.x;
    const int tid  = threadIdx.x;
    const int warp = tid >> 5;          // 0..4
    const int lane = tid & 31;
    const int cg   = lane >> 3;
    const int lg   = lane & 7;
    const int c0   = cg * 8;
    const int l0   = lg * 8;

    if (tid < NSEL) s_sel[tid] = g_topidx[b * NSEL + tid];
    if (tid < LC)   s_cid[tid] = claim[b * LC + tid];
    __syncthreads();
    for (int u = tid; u < NSEL * LT; u += 160) {
        int tt = u >> 6, l = u & 63;
        s_tid[u] = targets[((size_t)b * TT + s_sel[tt]) * LT + l];
    }
    __syncthreads();

    float acc[8][8];
#pragma unroll
    for (int i = 0; i < 8; ++i)
#pragma unroll
        for (int j = 0; j < 8; ++j) acc[i][j] = 0.f;

    const float4 zero4 = make_float4(0.f, 0.f, 0.f, 0.f);

    for (int chunk = 0; chunk < 10; ++chunk) {
        const int k0    = chunk * 32;
        const int kmax4 = (D - k0 + 3) >> 2;
        __syncthreads();

        for (int u = tid; u < 256; u += 160) {
            int c = u >> 3, q = u & 7;
            const float4* p = (const float4*)(emb + (size_t)s_cid[c] * D + k0) + q;
            float4 v = (q < kmax4) ? __ldg(p) : zero4;
            sA[q * 4 + 0][c] = v.x;
            sA[q * 4 + 1][c] = v.y;
            sA[q * 4 + 2][c] = v.z;
            sA[q * 4 + 3][c] = v.w;
        }
        for (int u = tid; u < NSEL * LT * 8; u += 160) {
            int lr = u >> 3, q = u & 7;
            const float4* p = (const float4*)(emb + (size_t)s_tid[lr] * D + k0) + q;
            float4 v = (q < kmax4) ? __ldg(p) : zero4;
            float* dst = &sB[lr >> 6][q * 4][lr & 63];
            dst[0 * 64] = v.x;
            dst[1 * 64] = v.y;
            dst[2 * 64] = v.z;
            dst[3 * 64] = v.w;
        }
        __syncthreads();

        const float (*Bw)[64] = sB[warp];
#pragma unroll 4
        for (int kk = 0; kk < 32; ++kk) {
            float4 a0 = *(const float4*)&sA[kk][c0];
            float4 a1 = *(const float4*)&sA[kk][c0 + 4];
            float4 b0 = *(const float4*)&Bw[kk][l0];
            float4 b1 = *(const float4*)&Bw[kk][l0 + 4];
            float av[8] = {a0.x, a0.y, a0.z, a0.w, a1.x, a1.y, a1.z, a1.w};
            float bv[8] = {b0.x, b0.y, b0.z, b0.w, b1.x, b1.y, b1.z, b1.w};
#pragma unroll
            for (int i = 0; i < 8; ++i)
#pragma unroll
                for (int j = 0; j < 8; ++j)
                    acc[i][j] = fmaf(av[i], bv[j], acc[i][j]);
        }
    }

    // L2-normalize each c-row over l (reduce across the 8-lane lg group),
    // write output: out[b][warp][c][l].
#pragma unroll
    for (int i = 0; i < 8; ++i) {
        float s2 = 0.f;
#pragma unroll
        for (int j = 0; j < 8; ++j) s2 = fmaf(acc[i][j], acc[i][j], s2);
        s2 += __shfl_xor_sync(0xffffffffu, s2, 1);
        s2 += __shfl_xor_sync(0xffffffffu, s2, 2);
        s2 += __shfl_xor_sync(0xffffffffu, s2, 4);
        float inv = 1.0f / sqrtf(s2);

        size_t off = (((size_t)(b * NSEL + warp) * LC) + (c0 + i)) * LT + l0;
        float4 v0 = make_float4(acc[i][0] * inv, acc[i][1] * inv,
                                acc[i][2] * inv, acc[i][3] * inv);
        float4 v1 = make_float4(acc[i][4] * inv, acc[i][5] * inv,
                                acc[i][6] * inv, acc[i][7] * inv);
        *(float4*)(out + off)     = v0;
        *(float4*)(out + off + 4) = v1;
    }
}

// ---------------------------------------------------------------------------
extern "C" void kernel_launch(void* const* d_in, const int* in_sizes, int n_in,
                              void* d_out, int out_size)
{
    // Identify inputs by element count (robust to metadata ordering):
    // claim 64*32=2048, targets 64*256*64=1048576, embeddings 50000*300=15000000.
    const int*   claim   = nullptr;
    const int*   targets = nullptr;
    const float* emb     = nullptr;
    for (int i = 0; i < n_in; ++i) {
        if (in_sizes[i] == BATCH * LC)            claim   = (const int*)d_in[i];
        else if (in_sizes[i] == BATCH * TT * LT)  targets = (const int*)d_in[i];
        else if (in_sizes[i] == VOCAB * D)        emb     = (const float*)d_in[i];
        // n (size 1) is the compile-time constant NSEL=5; ignored.
    }
    float* out = (float*)d_out;

    scores_kernel<<<dim3(TT / 4, BATCH, 1), 128>>>(claim, targets, emb);
    topk_kernel<<<BATCH, 32>>>();
    output_kernel<<<BATCH, 160>>>(claim, targets, emb, out);
}